// round 2
// baseline (speedup 1.0000x reference)
#include <cuda_runtime.h>

#define NN 100000
#define NE 1600000
#define DD 128
#define BN_EPS 1e-5f

// ---- scratch (static device globals; no runtime allocation) ----
__device__ float  g_deg[NN];
__device__ float  g_dinv[NN];
__device__ float4 g_agg[NN * (DD / 4)];      // aggregated x (after norm-scatter), [N][128]
__device__ float4 g_Wt[DD * DD / 4];         // Wt[k][d] = W[d][k]

// ---------------- small prep kernels ----------------

__global__ void k_deg_init() {
    int i = blockIdx.x * blockDim.x + threadIdx.x;
    if (i < NN) g_deg[i] = 1.0f;             // self-loop contributes 1
}

__global__ void k_count(const int* __restrict__ dst) {
    int e = blockIdx.x * blockDim.x + threadIdx.x;
    if (e < NE) atomicAdd(&g_deg[dst[e]], 1.0f);
}

__global__ void k_dinv() {
    int i = blockIdx.x * blockDim.x + threadIdx.x;
    if (i < NN) g_dinv[i] = rsqrtf(g_deg[i]);   // deg >= 1 always
}

// self-loop term: agg[i] = x[i] * dinv[i]^2  (initializes agg, no zeroing pass needed)
__global__ void k_self(const float4* __restrict__ x4) {
    int idx = blockIdx.x * blockDim.x + threadIdx.x;   // over N*32 float4s
    if (idx < NN * 32) {
        int node = idx >> 5;
        float w = g_dinv[node];
        w = w * w;
        float4 v = x4[idx];
        v.x *= w; v.y *= w; v.z *= w; v.w *= w;
        g_agg[idx] = v;
    }
}

// one-time transpose of W into Wt[k][d] so GEMM blocks can copy it coalesced + conflict-free
__global__ void k_transpose(const float* __restrict__ W) {
    int idx = blockIdx.x * blockDim.x + threadIdx.x;   // 16384
    if (idx < DD * DD) {
        int d = idx >> 7, k = idx & 127;
        ((float*)g_Wt)[k * DD + d] = W[idx];
    }
}

// ---------------- edge scatter: one warp per edge ----------------
// agg[dst] += x[src] * (dinv[src]*dinv[dst]) via 128-bit vector reductions.
__global__ void k_scatter(const int* __restrict__ src, const int* __restrict__ dst,
                          const float4* __restrict__ x4) {
    int gw   = (blockIdx.x * blockDim.x + threadIdx.x) >> 5;
    int lane = threadIdx.x & 31;
    if (gw >= NE) return;
    int s = __ldg(src + gw);
    int d = __ldg(dst + gw);
    float nrm = __ldg((const float*)&g_dinv[s]) * __ldg((const float*)&g_dinv[d]);
    float4 v = __ldg(&x4[s * 32 + lane]);
    v.x *= nrm; v.y *= nrm; v.z *= nrm; v.w *= nrm;
    float4* p = g_agg + d * 32 + lane;
    asm volatile("red.global.add.v4.f32 [%0], {%1,%2,%3,%4};"
                 :: "l"(p), "f"(v.x), "f"(v.y), "f"(v.z), "f"(v.w) : "memory");
}

// ---------------- fused GEMM + bias + BN(eval) + ReLU + residual + ReLU ----------------
// out = relu(relu((agg @ W^T)*s + t) + x),  s = gamma*rsqrt(var+eps),  t = (b-mean)*s + beta
#define GWARPS 8
#define RPW    4
#define CHUNK  (GWARPS * RPW)          // 32 rows per block-iteration
#define NCHUNK (NN / CHUNK)            // 3125 (exact)
#define GGRID  296                     // persistent: 2 blocks/SM

__global__ void __launch_bounds__(256, 2) k_gemm(
    const float4* __restrict__ x4,
    const float4* __restrict__ b4,  const float4* __restrict__ g4,
    const float4* __restrict__ be4, const float4* __restrict__ m4,
    const float4* __restrict__ v4,
    float4* __restrict__ out4)
{
    extern __shared__ float smem[];
    float4* sW4 = (float4*)smem;                       // Wt: [128][32] float4 (64KB)
    float*  sX  = smem + DD * DD;                      // per-warp [128][4] staging (16KB)

    int tid = threadIdx.x, lane = tid & 31, w = tid >> 5;

    // block-wide copy of Wt (coalesced, conflict-free)
    for (int i = tid; i < DD * DD / 4; i += 256) sW4[i] = g_Wt[i];

    // per-column epilogue constants (cols 4*lane .. 4*lane+3), computed once
    float4 bb = __ldg(&b4[lane]);
    float4 gg = __ldg(&g4[lane]);
    float4 be = __ldg(&be4[lane]);
    float4 mm = __ldg(&m4[lane]);
    float4 vv = __ldg(&v4[lane]);
    float4 sc, sh;
    sc.x = gg.x * rsqrtf(vv.x + BN_EPS); sc.y = gg.y * rsqrtf(vv.y + BN_EPS);
    sc.z = gg.z * rsqrtf(vv.z + BN_EPS); sc.w = gg.w * rsqrtf(vv.w + BN_EPS);
    sh.x = (bb.x - mm.x) * sc.x + be.x;  sh.y = (bb.y - mm.y) * sc.y + be.y;
    sh.z = (bb.z - mm.z) * sc.z + be.z;  sh.w = (bb.w - mm.w) * sc.w + be.w;
    __syncthreads();

    float* myX = sX + w * (DD * RPW);   // layout [k][r]

    for (int chunk = blockIdx.x; chunk < NCHUNK; chunk += gridDim.x) {
        int row0 = chunk * CHUNK + w * RPW;

        // stage 4 rows of agg, transposed to [k][r] so inner loop does one 16B broadcast
        {
            int r = lane & 3;
            const float4* grow = (const float4*)(g_agg + (row0 + r) * 32);
            #pragma unroll
            for (int j = 0; j < 4; j++) {
                int k4 = (lane >> 2) + j * 8;
                float4 v = grow[k4];
                myX[(4 * k4 + 0) * RPW + r] = v.x;
                myX[(4 * k4 + 1) * RPW + r] = v.y;
                myX[(4 * k4 + 2) * RPW + r] = v.z;
                myX[(4 * k4 + 3) * RPW + r] = v.w;
            }
        }
        __syncwarp();

        float4 acc0 = make_float4(0.f,0.f,0.f,0.f);
        float4 acc1 = acc0, acc2 = acc0, acc3 = acc0;

        #pragma unroll 8
        for (int k = 0; k < DD; k++) {
            float4 wv = sW4[k * 32 + lane];                 // conflict-free
            float4 av = *(const float4*)(myX + k * RPW);    // 16B broadcast
            acc0.x += av.x * wv.x; acc0.y += av.x * wv.y; acc0.z += av.x * wv.z; acc0.w += av.x * wv.w;
            acc1.x += av.y * wv.x; acc1.y += av.y * wv.y; acc1.z += av.y * wv.z; acc1.w += av.y * wv.w;
            acc2.x += av.z * wv.x; acc2.y += av.z * wv.y; acc2.z += av.z * wv.z; acc2.w += av.z * wv.w;
            acc3.x += av.w * wv.x; acc3.y += av.w * wv.y; acc3.z += av.w * wv.z; acc3.w += av.w * wv.w;
        }

        float4 acc[RPW] = {acc0, acc1, acc2, acc3};
        #pragma unroll
        for (int r = 0; r < RPW; r++) {
            int row = row0 + r;
            float4 xv = __ldg(&x4[row * 32 + lane]);
            float4 o;
            o.x = fmaxf(fmaxf(acc[r].x * sc.x + sh.x, 0.f) + xv.x, 0.f);
            o.y = fmaxf(fmaxf(acc[r].y * sc.y + sh.y, 0.f) + xv.y, 0.f);
            o.z = fmaxf(fmaxf(acc[r].z * sc.z + sh.z, 0.f) + xv.z, 0.f);
            o.w = fmaxf(fmaxf(acc[r].w * sc.w + sh.w, 0.f) + xv.w, 0.f);
            out4[row * 32 + lane] = o;
        }
        __syncwarp();
    }
}

// ---------------- launch ----------------

extern "C" void kernel_launch(void* const* d_in, const int* in_sizes, int n_in,
                              void* d_out, int out_size) {
    const float* x     = (const float*)d_in[0];
    const int*   eidx  = (const int*)  d_in[1];   // [2][E]: row0 = src, row1 = dst
    const float* W     = (const float*)d_in[2];
    const float* b     = (const float*)d_in[3];
    const float* gamma = (const float*)d_in[4];
    const float* beta  = (const float*)d_in[5];
    const float* rmean = (const float*)d_in[6];
    const float* rvar  = (const float*)d_in[7];
    float* out = (float*)d_out;

    const int* src = eidx;
    const int* dst = eidx + NE;

    k_deg_init<<<(NN + 255) / 256, 256>>>();
    k_count<<<(NE + 255) / 256, 256>>>(dst);
    k_dinv<<<(NN + 255) / 256, 256>>>();
    k_self<<<(NN * 32 + 255) / 256, 256>>>((const float4*)x);
    k_transpose<<<(DD * DD + 255) / 256, 256>>>(W);

    // one warp per edge
    k_scatter<<<(NE * 32 + 255) / 256, 256>>>(src, dst, (const float4*)x);

    static int smem_set = 0;
    int smem_bytes = (DD * DD + GWARPS * DD * RPW) * (int)sizeof(float);  // 81920
    if (!smem_set) {
        cudaFuncSetAttribute(k_gemm, cudaFuncAttributeMaxDynamicSharedMemorySize, smem_bytes);
        smem_set = 1;
    }
    k_gemm<<<GGRID, 256, smem_bytes>>>((const float4*)x,
                                       (const float4*)b, (const float4*)gamma,
                                       (const float4*)beta, (const float4*)rmean,
                                       (const float4*)rvar, (float4*)out);
}

// round 3
// speedup vs baseline: 1.4357x; 1.4357x over previous
#include <cuda_runtime.h>

#define NN 100000
#define NE 1600000
#define DD 128
#define BN_EPS 1e-5f
#define NSCAN ((NN + 1023) / 1024)    // 98

// ---- scratch (static device globals; no runtime allocation) ----
__device__ int    g_degi[NN];
__device__ float  g_dinv[NN];
__device__ int    g_off[NN + 1];
__device__ int    g_offtmp[NN];
__device__ int    g_cursor[NN];
__device__ int    g_bsum[128];
__device__ int    g_srcs[NE];
__device__ float4 g_Wt[DD * DD / 4];  // Wt[k][d] = W[d][k]

// ---------------- prep: degree count + CSR build ----------------

__global__ void k_zero() {
    int i = blockIdx.x * blockDim.x + threadIdx.x;
    if (i < NN) g_degi[i] = 0;
}

__global__ void k_count(const int* __restrict__ dst) {
    int e = blockIdx.x * blockDim.x + threadIdx.x;
    if (e < NE) atomicAdd(&g_degi[dst[e]], 1);
}

// block-level exclusive scan (1024 threads/block)
__global__ void k_scan1() {
    __shared__ int wsum[32];
    int tid = threadIdx.x;
    int gid = blockIdx.x * 1024 + tid;
    int v = (gid < NN) ? g_degi[gid] : 0;
    int x = v;
    #pragma unroll
    for (int o = 1; o < 32; o <<= 1) {
        int t = __shfl_up_sync(0xffffffffu, x, o);
        if ((tid & 31) >= o) x += t;
    }
    if ((tid & 31) == 31) wsum[tid >> 5] = x;
    __syncthreads();
    if (tid < 32) {
        int s = wsum[tid];
        #pragma unroll
        for (int o = 1; o < 32; o <<= 1) {
            int t = __shfl_up_sync(0xffffffffu, s, o);
            if (tid >= o) s += t;
        }
        wsum[tid] = s;
    }
    __syncthreads();
    int add  = (tid >= 32) ? wsum[(tid >> 5) - 1] : 0;
    int incl = x + add;
    if (gid < NN) g_offtmp[gid] = incl - v;     // exclusive
    if (tid == 1023) g_bsum[blockIdx.x] = incl; // block total
}

__global__ void k_scan2() {   // 1 thread: scan 98 block sums
    if (threadIdx.x == 0) {
        int run = 0;
        for (int i = 0; i < NSCAN; i++) {
            int v = g_bsum[i];
            g_bsum[i] = run;
            run += v;
        }
        g_off[NN] = NE;
    }
}

__global__ void k_scan3() {   // finalize offsets, cursors, dinv
    int i = blockIdx.x * blockDim.x + threadIdx.x;
    if (i < NN) {
        int off = g_offtmp[i] + g_bsum[i >> 10];
        g_off[i]    = off;
        g_cursor[i] = off;
        g_dinv[i]   = rsqrtf((float)g_degi[i] + 1.0f);   // +1 = self loop
    }
}

__global__ void k_bin(const int* __restrict__ src, const int* __restrict__ dst) {
    int e = blockIdx.x * blockDim.x + threadIdx.x;
    if (e < NE) {
        int d = dst[e];
        int pos = atomicAdd(&g_cursor[d], 1);
        g_srcs[pos] = src[e];
    }
}

__global__ void k_transpose(const float* __restrict__ W) {
    int idx = blockIdx.x * blockDim.x + threadIdx.x;
    if (idx < DD * DD) {
        int d = idx >> 7, k = idx & 127;
        ((float*)g_Wt)[k * DD + d] = W[idx];
    }
}

// ---------------- fused CSR-gather + GEMM + bias + BN + ReLU + residual + ReLU ----
// agg[d] = dinv[d]*( dinv[d]*x[d] + sum_{s in N(d)} dinv[s]*x[s] )
// out    = relu(relu((agg @ W^T)*sc + sh) + x)
#define GWARPS 8
#define RPW    4
#define CHUNK  (GWARPS * RPW)          // 32 rows per block-iteration
#define NCHUNK (NN / CHUNK)            // 3125 (exact)
#define GGRID  296

__global__ void __launch_bounds__(256, 2) k_gemm(
    const float4* __restrict__ x4,
    const float4* __restrict__ b4,  const float4* __restrict__ g4,
    const float4* __restrict__ be4, const float4* __restrict__ m4,
    const float4* __restrict__ v4,
    float4* __restrict__ out4)
{
    extern __shared__ float smem[];
    float4* sW4 = (float4*)smem;                       // Wt: [128][32] float4 (64KB)
    float*  sX  = smem + DD * DD;                      // per-warp [128][4] staging (16KB)

    int tid = threadIdx.x, lane = tid & 31, w = tid >> 5;

    for (int i = tid; i < DD * DD / 4; i += 256) sW4[i] = g_Wt[i];

    // per-column epilogue constants (cols 4*lane .. 4*lane+3)
    float4 bb = __ldg(&b4[lane]);
    float4 gg = __ldg(&g4[lane]);
    float4 be = __ldg(&be4[lane]);
    float4 mm = __ldg(&m4[lane]);
    float4 vv = __ldg(&v4[lane]);
    float4 sc, sh;
    sc.x = gg.x * rsqrtf(vv.x + BN_EPS); sc.y = gg.y * rsqrtf(vv.y + BN_EPS);
    sc.z = gg.z * rsqrtf(vv.z + BN_EPS); sc.w = gg.w * rsqrtf(vv.w + BN_EPS);
    sh.x = (bb.x - mm.x) * sc.x + be.x;  sh.y = (bb.y - mm.y) * sc.y + be.y;
    sh.z = (bb.z - mm.z) * sc.z + be.z;  sh.w = (bb.w - mm.w) * sc.w + be.w;
    __syncthreads();

    float* myX = sX + w * (DD * RPW);   // layout [k][r]

    for (int chunk = blockIdx.x; chunk < NCHUNK; chunk += gridDim.x) {
        int row0 = chunk * CHUNK + w * RPW;

        // ---- gather 4 rows (CSR by dst) into registers, write staging [k][r] ----
        #pragma unroll
        for (int r = 0; r < RPW; r++) {
            int node = row0 + r;
            float di = g_dinv[node];
            float4 acc = __ldg(&x4[node * 32 + lane]);       // self-loop term (× di)
            acc.x *= di; acc.y *= di; acc.z *= di; acc.w *= di;

            int beg = g_off[node], end = g_off[node + 1];
            for (int base = beg; base < end; base += 32) {
                int rem = end - base;
                int n = rem < 32 ? rem : 32;
                int sidx = (lane < n) ? __ldg(&g_srcs[base + lane]) : 0;
                float sdi = (lane < n) ? __ldg(&g_dinv[sidx]) : 0.0f;
                #pragma unroll 4
                for (int j = 0; j < n; j++) {
                    int   s  = __shfl_sync(0xffffffffu, sidx, j);
                    float ws = __shfl_sync(0xffffffffu, sdi,  j);
                    float4 v = __ldg(&x4[s * 32 + lane]);
                    acc.x += ws * v.x; acc.y += ws * v.y;
                    acc.z += ws * v.z; acc.w += ws * v.w;
                }
            }
            acc.x *= di; acc.y *= di; acc.z *= di; acc.w *= di;

            // transpose into staging: row r, cols 4*lane..4*lane+3
            myX[(4 * lane + 0) * RPW + r] = acc.x;
            myX[(4 * lane + 1) * RPW + r] = acc.y;
            myX[(4 * lane + 2) * RPW + r] = acc.z;
            myX[(4 * lane + 3) * RPW + r] = acc.w;
        }
        __syncwarp();

        // ---- GEMM: 4 rows × 128 cols ----
        float4 acc0 = make_float4(0.f,0.f,0.f,0.f);
        float4 acc1 = acc0, acc2 = acc0, acc3 = acc0;

        #pragma unroll 8
        for (int k = 0; k < DD; k++) {
            float4 wv = sW4[k * 32 + lane];
            float4 av = *(const float4*)(myX + k * RPW);
            acc0.x += av.x * wv.x; acc0.y += av.x * wv.y; acc0.z += av.x * wv.z; acc0.w += av.x * wv.w;
            acc1.x += av.y * wv.x; acc1.y += av.y * wv.y; acc1.z += av.y * wv.z; acc1.w += av.y * wv.w;
            acc2.x += av.z * wv.x; acc2.y += av.z * wv.y; acc2.z += av.z * wv.z; acc2.w += av.z * wv.w;
            acc3.x += av.w * wv.x; acc3.y += av.w * wv.y; acc3.z += av.w * wv.z; acc3.w += av.w * wv.w;
        }

        float4 acc[RPW] = {acc0, acc1, acc2, acc3};
        #pragma unroll
        for (int r = 0; r < RPW; r++) {
            int row = row0 + r;
            float4 xv = __ldg(&x4[row * 32 + lane]);
            float4 o;
            o.x = fmaxf(fmaxf(acc[r].x * sc.x + sh.x, 0.f) + xv.x, 0.f);
            o.y = fmaxf(fmaxf(acc[r].y * sc.y + sh.y, 0.f) + xv.y, 0.f);
            o.z = fmaxf(fmaxf(acc[r].z * sc.z + sh.z, 0.f) + xv.z, 0.f);
            o.w = fmaxf(fmaxf(acc[r].w * sc.w + sh.w, 0.f) + xv.w, 0.f);
            out4[row * 32 + lane] = o;
        }
        __syncwarp();
    }
}

// ---------------- launch ----------------

extern "C" void kernel_launch(void* const* d_in, const int* in_sizes, int n_in,
                              void* d_out, int out_size) {
    const float* x     = (const float*)d_in[0];
    const int*   eidx  = (const int*)  d_in[1];   // [2][E]: row0 = src, row1 = dst
    const float* W     = (const float*)d_in[2];
    const float* b     = (const float*)d_in[3];
    const float* gamma = (const float*)d_in[4];
    const float* beta  = (const float*)d_in[5];
    const float* rmean = (const float*)d_in[6];
    const float* rvar  = (const float*)d_in[7];
    float* out = (float*)d_out;

    const int* src = eidx;
    const int* dst = eidx + NE;

    k_zero<<<(NN + 255) / 256, 256>>>();
    k_count<<<(NE + 255) / 256, 256>>>(dst);
    k_scan1<<<NSCAN, 1024>>>();
    k_scan2<<<1, 32>>>();
    k_scan3<<<(NN + 255) / 256, 256>>>();
    k_bin<<<(NE + 255) / 256, 256>>>(src, dst);
    k_transpose<<<(DD * DD + 255) / 256, 256>>>(W);

    static int smem_set = 0;
    int smem_bytes = (DD * DD + GWARPS * DD * RPW) * (int)sizeof(float);  // 81920
    if (!smem_set) {
        cudaFuncSetAttribute(k_gemm, cudaFuncAttributeMaxDynamicSharedMemorySize, smem_bytes);
        smem_set = 1;
    }
    k_gemm<<<GGRID, 256, smem_bytes>>>((const float4*)x,
                                       (const float4*)b, (const float4*)gamma,
                                       (const float4*)beta, (const float4*)rmean,
                                       (const float4*)rvar, (float4*)out);
}

// round 4
// speedup vs baseline: 1.4715x; 1.0249x over previous
#include <cuda_runtime.h>

#define NN 100000
#define NE 1600000
#define DD 128
#define BN_EPS 1e-5f
#define NSCAN ((NN + 1023) / 1024)    // 98

typedef unsigned long long u64;

// ---- scratch (static device globals; no runtime allocation) ----
__device__ int    g_degi[NN];
__device__ float  g_dinv[NN];
__device__ int    g_off[NN + 1];
__device__ int    g_offtmp[NN];
__device__ int    g_cursor[NN];
__device__ int    g_bsum[128];
__device__ int    g_tick;
__device__ int    g_srcs[NE];
__device__ float4 g_Wt[DD * DD / 4];  // Wt[k][d] = W[d][k]

// ---------------- packed f32x2 helpers ----------------
__device__ __forceinline__ u64 packf2(float lo, float hi) {
    u64 r; asm("mov.b64 %0, {%1, %2};" : "=l"(r) : "f"(lo), "f"(hi)); return r;
}
__device__ __forceinline__ void unpackf2(u64 v, float& lo, float& hi) {
    asm("mov.b64 {%0, %1}, %2;" : "=f"(lo), "=f"(hi) : "l"(v));
}
#define FMA2(acc, a, b) asm("fma.rn.f32x2 %0, %1, %2, %0;" : "+l"(acc) : "l"(a), "l"(b))

// ---------------- prep: degree count + CSR build ----------------

__global__ void k_count(const int* __restrict__ dst) {
    int e = blockIdx.x * blockDim.x + threadIdx.x;
    if (e < NE) atomicAdd(&g_degi[dst[e]], 1);
}

__global__ void k_scan1() {
    __shared__ int wsum[32];
    int tid = threadIdx.x;
    int gid = blockIdx.x * 1024 + tid;
    int v = (gid < NN) ? g_degi[gid] : 0;
    int x = v;
    #pragma unroll
    for (int o = 1; o < 32; o <<= 1) {
        int t = __shfl_up_sync(0xffffffffu, x, o);
        if ((tid & 31) >= o) x += t;
    }
    if ((tid & 31) == 31) wsum[tid >> 5] = x;
    __syncthreads();
    if (tid < 32) {
        int s = wsum[tid];
        #pragma unroll
        for (int o = 1; o < 32; o <<= 1) {
            int t = __shfl_up_sync(0xffffffffu, s, o);
            if (tid >= o) s += t;
        }
        wsum[tid] = s;
    }
    __syncthreads();
    int add  = (tid >= 32) ? wsum[(tid >> 5) - 1] : 0;
    int incl = x + add;
    if (gid < NN) g_offtmp[gid] = incl - v;
    if (tid == 1023) g_bsum[blockIdx.x] = incl;
}

__global__ void k_scan2() {   // parallel scan of 98 block sums (128 threads)
    __shared__ int wsum[4];
    int t = threadIdx.x, lane = t & 31, w = t >> 5;
    int v = (t < NSCAN) ? g_bsum[t] : 0;
    int x = v;
    #pragma unroll
    for (int o = 1; o < 32; o <<= 1) {
        int tm = __shfl_up_sync(0xffffffffu, x, o);
        if (lane >= o) x += tm;
    }
    if (lane == 31) wsum[w] = x;
    __syncthreads();
    if (t == 0) {
        int run = 0;
        #pragma unroll
        for (int i = 0; i < 4; i++) { int q = wsum[i]; wsum[i] = run; run += q; }
        g_off[NN] = NE;
        g_tick = 0;              // reset GEMM work-steal ticket each replay
    }
    __syncthreads();
    if (t < NSCAN) g_bsum[t] = x - v + wsum[w];   // exclusive
}

__global__ void k_scan3() {
    int i = blockIdx.x * blockDim.x + threadIdx.x;
    if (i < NN) {
        int off = g_offtmp[i] + g_bsum[i >> 10];
        g_off[i]    = off;
        g_cursor[i] = off;
        g_dinv[i]   = rsqrtf((float)g_degi[i] + 1.0f);
    }
}

__global__ void k_bin(const int* __restrict__ src, const int* __restrict__ dst) {
    int e = blockIdx.x * blockDim.x + threadIdx.x;
    if (e < NE) {
        int d = dst[e];
        int pos = atomicAdd(&g_cursor[d], 1);
        g_srcs[pos] = src[e];
    }
}

__global__ void k_transpose(const float* __restrict__ W) {
    int idx = blockIdx.x * blockDim.x + threadIdx.x;
    if (idx < DD * DD) {
        int d = idx >> 7, k = idx & 127;
        ((float*)g_Wt)[k * DD + d] = W[idx];
    }
}

// ---------------- fused CSR-gather + GEMM(f32x2) + BN + ReLU + res + ReLU ----
#define GWARPS 8
#define RPW    8
#define CHUNK  (GWARPS * RPW)                 // 64
#define NCHUNK ((NN + CHUNK - 1) / CHUNK)     // 1563 (last chunk partial)
#define GGRID  296

__device__ __forceinline__ float4 gather_row(int node, int lane,
                                             const float4* __restrict__ x4) {
    float di = g_dinv[node];
    float4 acc = __ldg(&x4[node * 32 + lane]);       // self-loop term
    acc.x *= di; acc.y *= di; acc.z *= di; acc.w *= di;
    int beg = g_off[node], end = g_off[node + 1];
    for (int base = beg; base < end; base += 32) {
        int rem = end - base;
        int n = rem < 32 ? rem : 32;
        int   sidx = (lane < n) ? __ldg(&g_srcs[base + lane]) : 0;
        float sdi  = (lane < n) ? g_dinv[sidx] : 0.0f;
        #pragma unroll 4
        for (int jj = 0; jj < n; jj++) {
            int   s  = __shfl_sync(0xffffffffu, sidx, jj);
            float ws = __shfl_sync(0xffffffffu, sdi,  jj);
            float4 v = __ldg(&x4[s * 32 + lane]);
            acc.x += ws * v.x; acc.y += ws * v.y;
            acc.z += ws * v.z; acc.w += ws * v.w;
        }
    }
    acc.x *= di; acc.y *= di; acc.z *= di; acc.w *= di;
    return acc;
}

__global__ void __launch_bounds__(256, 2) k_gemm(
    const float4* __restrict__ x4,
    const float4* __restrict__ b4,  const float4* __restrict__ g4,
    const float4* __restrict__ be4, const float4* __restrict__ m4,
    const float4* __restrict__ v4,
    float4* __restrict__ out4)
{
    extern __shared__ float smem[];
    float4* sW4 = (float4*)smem;                       // Wt: [128][32] float4 (64KB)
    float*  sXa = smem + DD * DD;                      // staging: 8 warps × 1KB floats (32KB)
    __shared__ int s_chunk;

    int tid = threadIdx.x, lane = tid & 31, w = tid >> 5;
    int lrot = lane & 3;

    for (int i = tid; i < DD * DD / 4; i += 256) sW4[i] = g_Wt[i];

    // per-column epilogue constants (cols 4*lane .. 4*lane+3)
    float4 bb = __ldg(&b4[lane]);
    float4 gg = __ldg(&g4[lane]);
    float4 be = __ldg(&be4[lane]);
    float4 mm = __ldg(&m4[lane]);
    float4 vv = __ldg(&v4[lane]);
    float4 sc, sh;
    sc.x = gg.x * rsqrtf(vv.x + BN_EPS); sc.y = gg.y * rsqrtf(vv.y + BN_EPS);
    sc.z = gg.z * rsqrtf(vv.z + BN_EPS); sc.w = gg.w * rsqrtf(vv.w + BN_EPS);
    sh.x = (bb.x - mm.x) * sc.x + be.x;  sh.y = (bb.y - mm.y) * sc.y + be.y;
    sh.z = (bb.z - mm.z) * sc.z + be.z;  sh.w = (bb.w - mm.w) * sc.w + be.w;

    float* myX = sXa + w * (DD * RPW);   // [k][pair-slot] layout, pair-rotated by lane
    __syncthreads();

    while (true) {
        if (tid == 0) s_chunk = atomicAdd(&g_tick, 1);
        __syncthreads();
        int chunk = s_chunk;
        if (chunk >= NCHUNK) break;
        int row0 = chunk * CHUNK + w * RPW;

        // ---- gather 8 rows as 4 pairs; store pair-packed b64s (swizzled) ----
        #pragma unroll
        for (int j2 = 0; j2 < 4; j2++) {
            int nA = row0 + 2 * j2, nB = nA + 1;
            float4 a = (nA < NN) ? gather_row(nA, lane, x4) : make_float4(0.f,0.f,0.f,0.f);
            float4 b = (nB < NN) ? gather_row(nB, lane, x4) : make_float4(0.f,0.f,0.f,0.f);
            int rp = (j2 + lrot) & 3;
            float* base = myX + lane * 32 + 2 * rp;     // k-block = lane
            *(u64*)(base +  0) = packf2(a.x, b.x);      // k=4*lane+0
            *(u64*)(base +  8) = packf2(a.y, b.y);      // k=4*lane+1
            *(u64*)(base + 16) = packf2(a.z, b.z);
            *(u64*)(base + 24) = packf2(a.w, b.w);
        }
        __syncwarp();

        // ---- GEMM: 8 rows (4 f32x2 pairs) × 4 cols per thread ----
        u64 acc[4][4];
        #pragma unroll
        for (int j = 0; j < 4; j++)
            #pragma unroll
            for (int c = 0; c < 4; c++) acc[j][c] = 0ull;

        for (int kk = 0; kk < DD; kk += 16) {
            #pragma unroll
            for (int t = 0; t < 16; t++) {
                int k = kk + t;
                const float4 wv = sW4[k * 32 + lane];
                u64 w0 = packf2(wv.x, wv.x), w1 = packf2(wv.y, wv.y);
                u64 w2 = packf2(wv.z, wv.z), w3 = packf2(wv.w, wv.w);
                const ulonglong2 avA = *(const ulonglong2*)(myX + k * 8);
                const ulonglong2 avB = *(const ulonglong2*)(myX + k * 8 + 4);
                u64 sl[4] = {avA.x, avA.y, avB.x, avB.y};
                const int rot = (t >> 2) & 3;            // = (k>>2)&3, compile-time
                #pragma unroll
                for (int p = 0; p < 4; p++) {
                    const int j = (p + 4 - rot) & 3;     // pair index stored at slot p
                    FMA2(acc[j][0], sl[p], w0);
                    FMA2(acc[j][1], sl[p], w1);
                    FMA2(acc[j][2], sl[p], w2);
                    FMA2(acc[j][3], sl[p], w3);
                }
            }
        }

        // ---- epilogue ----
        #pragma unroll
        for (int j = 0; j < 4; j++) {
            int rE = row0 + 2 * j, rO = rE + 1;
            float e0,o0,e1,o1,e2,o2,e3,o3;
            unpackf2(acc[j][0], e0, o0); unpackf2(acc[j][1], e1, o1);
            unpackf2(acc[j][2], e2, o2); unpackf2(acc[j][3], e3, o3);
            if (rE < NN) {
                float4 xv = __ldg(&x4[rE * 32 + lane]);
                float4 o;
                o.x = fmaxf(fmaxf(e0 * sc.x + sh.x, 0.f) + xv.x, 0.f);
                o.y = fmaxf(fmaxf(e1 * sc.y + sh.y, 0.f) + xv.y, 0.f);
                o.z = fmaxf(fmaxf(e2 * sc.z + sh.z, 0.f) + xv.z, 0.f);
                o.w = fmaxf(fmaxf(e3 * sc.w + sh.w, 0.f) + xv.w, 0.f);
                out4[rE * 32 + lane] = o;
            }
            if (rO < NN) {
                float4 xv = __ldg(&x4[rO * 32 + lane]);
                float4 o;
                o.x = fmaxf(fmaxf(o0 * sc.x + sh.x, 0.f) + xv.x, 0.f);
                o.y = fmaxf(fmaxf(o1 * sc.y + sh.y, 0.f) + xv.y, 0.f);
                o.z = fmaxf(fmaxf(o2 * sc.z + sh.z, 0.f) + xv.z, 0.f);
                o.w = fmaxf(fmaxf(o3 * sc.w + sh.w, 0.f) + xv.w, 0.f);
                out4[rO * 32 + lane] = o;
            }
        }
        __syncthreads();   // ticket reuse fence
    }
}

// ---------------- launch ----------------

extern "C" void kernel_launch(void* const* d_in, const int* in_sizes, int n_in,
                              void* d_out, int out_size) {
    const float* x     = (const float*)d_in[0];
    const int*   eidx  = (const int*)  d_in[1];   // [2][E]: row0 = src, row1 = dst
    const float* W     = (const float*)d_in[2];
    const float* b     = (const float*)d_in[3];
    const float* gamma = (const float*)d_in[4];
    const float* beta  = (const float*)d_in[5];
    const float* rmean = (const float*)d_in[6];
    const float* rvar  = (const float*)d_in[7];
    float* out = (float*)d_out;

    const int* src = eidx;
    const int* dst = eidx + NE;

    static void* degi_ptr = nullptr;
    static int smem_set = 0;
    int smem_bytes = (DD * DD + GWARPS * DD * RPW) * (int)sizeof(float);  // 98304
    if (!smem_set) {
        cudaGetSymbolAddress(&degi_ptr, g_degi);
        cudaFuncSetAttribute(k_gemm, cudaFuncAttributeMaxDynamicSharedMemorySize, smem_bytes);
        smem_set = 1;
    }

    cudaMemsetAsync(degi_ptr, 0, NN * sizeof(int));
    k_count<<<(NE + 255) / 256, 256>>>(dst);
    k_scan1<<<NSCAN, 1024>>>();
    k_scan2<<<1, 128>>>();
    k_scan3<<<(NN + 255) / 256, 256>>>();
    k_bin<<<(NE + 255) / 256, 256>>>(src, dst);
    k_transpose<<<(DD * DD + 255) / 256, 256>>>(W);

    k_gemm<<<GGRID, 256, smem_bytes>>>((const float4*)x,
                                       (const float4*)b, (const float4*)gamma,
                                       (const float4*)beta, (const float4*)rmean,
                                       (const float4*)rvar, (float4*)out);
}

// round 5
// speedup vs baseline: 1.6241x; 1.1037x over previous
#include <cuda_runtime.h>

#define NN 100000
#define NE 1600000
#define DD 128
#define BN_EPS 1e-5f
#define NSCAN ((NN + 1023) / 1024)    // 98

typedef unsigned long long u64;

// ---- scratch (static device globals; no runtime allocation) ----
__device__ int    g_degi[NN];
__device__ float  g_dinv[NN];
__device__ int    g_off[NN + 1];
__device__ int    g_offtmp[NN];
__device__ int    g_cursor[NN];
__device__ int    g_bsum[128];
__device__ int    g_tick;
__device__ int    g_srcs[NE];
__device__ float4 g_agg[NN * 32];     // normalized aggregate, [N][128]
__device__ float4 g_Wt[DD * DD / 4];  // Wt[k][d] = W[d][k]

// ---------------- packed f32x2 helpers ----------------
__device__ __forceinline__ u64 packf2(float lo, float hi) {
    u64 r; asm("mov.b64 %0, {%1, %2};" : "=l"(r) : "f"(lo), "f"(hi)); return r;
}
__device__ __forceinline__ void unpackf2(u64 v, float& lo, float& hi) {
    asm("mov.b64 {%0, %1}, %2;" : "=f"(lo), "=f"(hi) : "l"(v));
}
#define FMA2(acc, a, b) asm("fma.rn.f32x2 %0, %1, %2, %0;" : "+l"(acc) : "l"(a), "l"(b))

// ---------------- prep: degree count + CSR build ----------------

__global__ void k_count(const int* __restrict__ dst) {
    int e = blockIdx.x * blockDim.x + threadIdx.x;
    if (e < NE) atomicAdd(&g_degi[dst[e]], 1);
}

__global__ void k_scan1() {
    __shared__ int wsum[32];
    int tid = threadIdx.x;
    int gid = blockIdx.x * 1024 + tid;
    int v = (gid < NN) ? g_degi[gid] : 0;
    int x = v;
    #pragma unroll
    for (int o = 1; o < 32; o <<= 1) {
        int t = __shfl_up_sync(0xffffffffu, x, o);
        if ((tid & 31) >= o) x += t;
    }
    if ((tid & 31) == 31) wsum[tid >> 5] = x;
    __syncthreads();
    if (tid < 32) {
        int s = wsum[tid];
        #pragma unroll
        for (int o = 1; o < 32; o <<= 1) {
            int t = __shfl_up_sync(0xffffffffu, s, o);
            if (tid >= o) s += t;
        }
        wsum[tid] = s;
    }
    __syncthreads();
    int add  = (tid >= 32) ? wsum[(tid >> 5) - 1] : 0;
    int incl = x + add;
    if (gid < NN) g_offtmp[gid] = incl - v;
    if (tid == 1023) g_bsum[blockIdx.x] = incl;
}

__global__ void k_scan2() {   // parallel scan of 98 block sums
    __shared__ int wsum[4];
    int t = threadIdx.x, lane = t & 31, w = t >> 5;
    int v = (t < NSCAN) ? g_bsum[t] : 0;
    int x = v;
    #pragma unroll
    for (int o = 1; o < 32; o <<= 1) {
        int tm = __shfl_up_sync(0xffffffffu, x, o);
        if (lane >= o) x += tm;
    }
    if (lane == 31) wsum[w] = x;
    __syncthreads();
    if (t == 0) {
        int run = 0;
        #pragma unroll
        for (int i = 0; i < 4; i++) { int q = wsum[i]; wsum[i] = run; run += q; }
        g_off[NN] = NE;
        g_tick = 0;              // reset GEMM work-steal ticket each replay
    }
    __syncthreads();
    if (t < NSCAN) g_bsum[t] = x - v + wsum[w];
}

__global__ void k_scan3() {
    int i = blockIdx.x * blockDim.x + threadIdx.x;
    if (i < NN) {
        int off = g_offtmp[i] + g_bsum[i >> 10];
        g_off[i]    = off;
        g_cursor[i] = off;
        g_dinv[i]   = rsqrtf((float)g_degi[i] + 1.0f);
    }
}

__global__ void k_bin(const int* __restrict__ src, const int* __restrict__ dst) {
    int e = blockIdx.x * blockDim.x + threadIdx.x;
    if (e < NE) {
        int d = dst[e];
        int pos = atomicAdd(&g_cursor[d], 1);
        g_srcs[pos] = src[e];
    }
}

__global__ void k_transpose(const float* __restrict__ W) {
    int idx = blockIdx.x * blockDim.x + threadIdx.x;
    if (idx < DD * DD) {
        int d = idx >> 7, k = idx & 127;
        ((float*)g_Wt)[k * DD + d] = W[idx];
    }
}

// ---------------- gather: one warp per node, high occupancy ----------------
#define GATHER_BLOCKS 1184
#define GATHER_WPB    8

__global__ void __launch_bounds__(256) k_gather(const float4* __restrict__ x4) {
    int lane = threadIdx.x & 31;
    int gw0  = blockIdx.x * GATHER_WPB + (threadIdx.x >> 5);
    const int nwarps = GATHER_BLOCKS * GATHER_WPB;

    for (int node = gw0; node < NN; node += nwarps) {
        float di = g_dinv[node];
        float4 acc = __ldg(&x4[node * 32 + lane]);       // self-loop term
        acc.x *= di; acc.y *= di; acc.z *= di; acc.w *= di;

        int beg = g_off[node], end = g_off[node + 1];
        for (int base = beg; base < end; base += 32) {
            int rem = end - base;
            int n = rem < 32 ? rem : 32;
            int   sidx = (lane < n) ? __ldg(&g_srcs[base + lane]) : 0;
            float sdi  = (lane < n) ? g_dinv[sidx] : 0.0f;
            #pragma unroll 8
            for (int jj = 0; jj < n; jj++) {
                int   s  = __shfl_sync(0xffffffffu, sidx, jj);
                float ws = __shfl_sync(0xffffffffu, sdi,  jj);
                float4 v = __ldg(&x4[s * 32 + lane]);
                acc.x += ws * v.x; acc.y += ws * v.y;
                acc.z += ws * v.z; acc.w += ws * v.w;
            }
        }
        acc.x *= di; acc.y *= di; acc.z *= di; acc.w *= di;
        g_agg[node * 32 + lane] = acc;
    }
}

// ---------------- GEMM(f32x2) + BN + ReLU + res + ReLU ----------------
#define GWARPS 8
#define RPW    8
#define CHUNK  (GWARPS * RPW)                 // 64
#define NCHUNK ((NN + CHUNK - 1) / CHUNK)     // 1563
#define GGRID  296

__global__ void __launch_bounds__(256, 2) k_gemm(
    const float4* __restrict__ x4,
    const float4* __restrict__ b4,  const float4* __restrict__ g4,
    const float4* __restrict__ be4, const float4* __restrict__ m4,
    const float4* __restrict__ v4,
    float4* __restrict__ out4)
{
    extern __shared__ float smem[];
    float4* sW4 = (float4*)smem;                       // Wt: 64KB
    float*  sXa = smem + DD * DD;                      // staging: 32KB
    __shared__ int s_chunk;

    int tid = threadIdx.x, lane = tid & 31, w = tid >> 5;
    int lrot = lane & 3;

    for (int i = tid; i < DD * DD / 4; i += 256) sW4[i] = g_Wt[i];

    float4 bb = __ldg(&b4[lane]);
    float4 gg = __ldg(&g4[lane]);
    float4 be = __ldg(&be4[lane]);
    float4 mm = __ldg(&m4[lane]);
    float4 vv = __ldg(&v4[lane]);
    float4 sc, sh;
    sc.x = gg.x * rsqrtf(vv.x + BN_EPS); sc.y = gg.y * rsqrtf(vv.y + BN_EPS);
    sc.z = gg.z * rsqrtf(vv.z + BN_EPS); sc.w = gg.w * rsqrtf(vv.w + BN_EPS);
    sh.x = (bb.x - mm.x) * sc.x + be.x;  sh.y = (bb.y - mm.y) * sc.y + be.y;
    sh.z = (bb.z - mm.z) * sc.z + be.z;  sh.w = (bb.w - mm.w) * sc.w + be.w;

    float* myX = sXa + w * (DD * RPW);
    __syncthreads();

    while (true) {
        if (tid == 0) s_chunk = atomicAdd(&g_tick, 1);
        __syncthreads();
        int chunk = s_chunk;
        if (chunk >= NCHUNK) break;
        int row0 = chunk * CHUNK + w * RPW;

        // ---- load 8 agg rows as 4 pairs; store pair-packed b64s (swizzled) ----
        #pragma unroll
        for (int j2 = 0; j2 < 4; j2++) {
            int nA = row0 + 2 * j2, nB = nA + 1;
            float4 a = (nA < NN) ? __ldg(&g_agg[nA * 32 + lane]) : make_float4(0.f,0.f,0.f,0.f);
            float4 b = (nB < NN) ? __ldg(&g_agg[nB * 32 + lane]) : make_float4(0.f,0.f,0.f,0.f);
            int rp = (j2 + lrot) & 3;
            float* base = myX + lane * 32 + 2 * rp;
            *(u64*)(base +  0) = packf2(a.x, b.x);
            *(u64*)(base +  8) = packf2(a.y, b.y);
            *(u64*)(base + 16) = packf2(a.z, b.z);
            *(u64*)(base + 24) = packf2(a.w, b.w);
        }
        __syncwarp();

        // ---- GEMM: 8 rows (4 f32x2 pairs) × 4 cols per thread ----
        u64 acc[4][4];
        #pragma unroll
        for (int j = 0; j < 4; j++)
            #pragma unroll
            for (int c = 0; c < 4; c++) acc[j][c] = 0ull;

        for (int kk = 0; kk < DD; kk += 16) {
            #pragma unroll
            for (int t = 0; t < 16; t++) {
                int k = kk + t;
                const float4 wv = sW4[k * 32 + lane];
                u64 w0 = packf2(wv.x, wv.x), w1 = packf2(wv.y, wv.y);
                u64 w2 = packf2(wv.z, wv.z), w3 = packf2(wv.w, wv.w);
                const ulonglong2 avA = *(const ulonglong2*)(myX + k * 8);
                const ulonglong2 avB = *(const ulonglong2*)(myX + k * 8 + 4);
                u64 sl[4] = {avA.x, avA.y, avB.x, avB.y};
                const int rot = (t >> 2) & 3;
                #pragma unroll
                for (int p = 0; p < 4; p++) {
                    const int j = (p + 4 - rot) & 3;
                    FMA2(acc[j][0], sl[p], w0);
                    FMA2(acc[j][1], sl[p], w1);
                    FMA2(acc[j][2], sl[p], w2);
                    FMA2(acc[j][3], sl[p], w3);
                }
            }
        }

        // ---- epilogue ----
        #pragma unroll
        for (int j = 0; j < 4; j++) {
            int rE = row0 + 2 * j, rO = rE + 1;
            float e0,o0,e1,o1,e2,o2,e3,o3;
            unpackf2(acc[j][0], e0, o0); unpackf2(acc[j][1], e1, o1);
            unpackf2(acc[j][2], e2, o2); unpackf2(acc[j][3], e3, o3);
            if (rE < NN) {
                float4 xv = __ldg(&x4[rE * 32 + lane]);
                float4 o;
                o.x = fmaxf(fmaxf(e0 * sc.x + sh.x, 0.f) + xv.x, 0.f);
                o.y = fmaxf(fmaxf(e1 * sc.y + sh.y, 0.f) + xv.y, 0.f);
                o.z = fmaxf(fmaxf(e2 * sc.z + sh.z, 0.f) + xv.z, 0.f);
                o.w = fmaxf(fmaxf(e3 * sc.w + sh.w, 0.f) + xv.w, 0.f);
                out4[rE * 32 + lane] = o;
            }
            if (rO < NN) {
                float4 xv = __ldg(&x4[rO * 32 + lane]);
                float4 o;
                o.x = fmaxf(fmaxf(o0 * sc.x + sh.x, 0.f) + xv.x, 0.f);
                o.y = fmaxf(fmaxf(o1 * sc.y + sh.y, 0.f) + xv.y, 0.f);
                o.z = fmaxf(fmaxf(o2 * sc.z + sh.z, 0.f) + xv.z, 0.f);
                o.w = fmaxf(fmaxf(o3 * sc.w + sh.w, 0.f) + xv.w, 0.f);
                out4[rO * 32 + lane] = o;
            }
        }
        __syncthreads();
    }
}

// ---------------- launch ----------------

extern "C" void kernel_launch(void* const* d_in, const int* in_sizes, int n_in,
                              void* d_out, int out_size) {
    const float* x     = (const float*)d_in[0];
    const int*   eidx  = (const int*)  d_in[1];   // [2][E]: row0 = src, row1 = dst
    const float* W     = (const float*)d_in[2];
    const float* b     = (const float*)d_in[3];
    const float* gamma = (const float*)d_in[4];
    const float* beta  = (const float*)d_in[5];
    const float* rmean = (const float*)d_in[6];
    const float* rvar  = (const float*)d_in[7];
    float* out = (float*)d_out;

    const int* src = eidx;
    const int* dst = eidx + NE;

    static void* degi_ptr = nullptr;
    static int smem_set = 0;
    int smem_bytes = (DD * DD + GWARPS * DD * RPW) * (int)sizeof(float);  // 98304
    if (!smem_set) {
        cudaGetSymbolAddress(&degi_ptr, g_degi);
        cudaFuncSetAttribute(k_gemm, cudaFuncAttributeMaxDynamicSharedMemorySize, smem_bytes);
        smem_set = 1;
    }

    cudaMemsetAsync(degi_ptr, 0, NN * sizeof(int));
    k_count<<<(NE + 255) / 256, 256>>>(dst);
    k_scan1<<<NSCAN, 1024>>>();
    k_scan2<<<1, 128>>>();
    k_scan3<<<(NN + 255) / 256, 256>>>();
    k_bin<<<(NE + 255) / 256, 256>>>(src, dst);
    k_transpose<<<(DD * DD + 255) / 256, 256>>>(W);

    k_gather<<<GATHER_BLOCKS, 256>>>((const float4*)x);

    k_gemm<<<GGRID, 256, smem_bytes>>>((const float4*)x,
                                       (const float4*)b, (const float4*)gamma,
                                       (const float4*)beta, (const float4*)rmean,
                                       (const float4*)rvar, (float4*)out);
}

// round 6
// speedup vs baseline: 1.7280x; 1.0640x over previous
#include <cuda_runtime.h>
#include <cuda_fp16.h>

#define NN 100000
#define NE 1600000
#define DD 128
#define BN_EPS 1e-5f
#define NSCAN ((NN + 1023) / 1024)    // 98

typedef unsigned long long u64;

// ---- scratch (static device globals; no runtime allocation) ----
__device__ int    g_degi[NN];
__device__ float  g_dinv[NN];
__device__ int    g_off[NN + 1];
__device__ int    g_offtmp[NN];
__device__ int    g_cursor[NN];
__device__ int    g_bsum[128];
__device__ int    g_tick;
__device__ int    g_srcs[NE];
__device__ uint2  g_xh[NN * 32];      // fp16 copy of x: [N][128] halfs, 8B-vec per lane
__device__ float4 g_agg[NN * 32];     // normalized aggregate, [N][128] fp32
__device__ float4 g_Wt[DD * DD / 4];  // Wt[k][d] = W[d][k]

// ---------------- packed f32x2 helpers ----------------
__device__ __forceinline__ u64 packf2(float lo, float hi) {
    u64 r; asm("mov.b64 %0, {%1, %2};" : "=l"(r) : "f"(lo), "f"(hi)); return r;
}
__device__ __forceinline__ void unpackf2(u64 v, float& lo, float& hi) {
    asm("mov.b64 {%0, %1}, %2;" : "=f"(lo), "=f"(hi) : "l"(v));
}
#define FMA2(acc, a, b) asm("fma.rn.f32x2 %0, %1, %2, %0;" : "+l"(acc) : "l"(a), "l"(b))

// ---------------- prep: degree count + CSR build ----------------

__global__ void k_count(const int* __restrict__ dst) {
    int e = blockIdx.x * blockDim.x + threadIdx.x;
    if (e < NE) atomicAdd(&g_degi[dst[e]], 1);
}

__global__ void k_scan1() {
    __shared__ int wsum[32];
    int tid = threadIdx.x;
    int gid = blockIdx.x * 1024 + tid;
    int v = (gid < NN) ? g_degi[gid] : 0;
    int x = v;
    #pragma unroll
    for (int o = 1; o < 32; o <<= 1) {
        int t = __shfl_up_sync(0xffffffffu, x, o);
        if ((tid & 31) >= o) x += t;
    }
    if ((tid & 31) == 31) wsum[tid >> 5] = x;
    __syncthreads();
    if (tid < 32) {
        int s = wsum[tid];
        #pragma unroll
        for (int o = 1; o < 32; o <<= 1) {
            int t = __shfl_up_sync(0xffffffffu, s, o);
            if (tid >= o) s += t;
        }
        wsum[tid] = s;
    }
    __syncthreads();
    int add  = (tid >= 32) ? wsum[(tid >> 5) - 1] : 0;
    int incl = x + add;
    if (gid < NN) g_offtmp[gid] = incl - v;
    if (tid == 1023) g_bsum[blockIdx.x] = incl;
}

// merged scan2+scan3: every block scans the 98 block sums (cheap, redundant),
// then finalizes offsets / cursors / dinv for its slice of nodes.
__global__ void k_scan23() {
    __shared__ int pre[NSCAN];   // exclusive prefix of block sums
    __shared__ int wtot[4];
    int tid = threadIdx.x, lane = tid & 31, w = tid >> 5;

    if (tid < 128) {
        int v = (tid < NSCAN) ? g_bsum[tid] : 0;
        int x = v;
        #pragma unroll
        for (int o = 1; o < 32; o <<= 1) {
            int t = __shfl_up_sync(0xffffffffu, x, o);
            if (lane >= o) x += t;
        }
        if (lane == 31) wtot[w] = x;
        __syncwarp();
    }
    __syncthreads();
    if (tid == 0) {
        int run = 0;
        #pragma unroll
        for (int i = 0; i < 4; i++) { int q = wtot[i]; wtot[i] = run; run += q; }
    }
    __syncthreads();
    if (tid < 128) {
        int v = (tid < NSCAN) ? g_bsum[tid] : 0;
        int x = v;
        #pragma unroll
        for (int o = 1; o < 32; o <<= 1) {
            int t = __shfl_up_sync(0xffffffffu, x, o);
            if (lane >= o) x += t;
        }
        if (tid < NSCAN) pre[tid] = x - v + wtot[w];
    }
    __syncthreads();

    int i = blockIdx.x * blockDim.x + tid;
    if (i < NN) {
        int off = g_offtmp[i] + pre[i >> 10];
        g_off[i]    = off;
        g_cursor[i] = off;
        g_dinv[i]   = rsqrtf((float)g_degi[i] + 1.0f);
    }
    if (blockIdx.x == 0 && tid == 0) {
        g_off[NN] = NE;
        g_tick = 0;              // reset GEMM work-steal ticket each replay
    }
}

__global__ void k_bin(const int* __restrict__ src, const int* __restrict__ dst) {
    int e = blockIdx.x * blockDim.x + threadIdx.x;
    if (e < NE) {
        int d = dst[e];
        int pos = atomicAdd(&g_cursor[d], 1);
        g_srcs[pos] = src[e];
    }
}

__global__ void k_transpose(const float* __restrict__ W) {
    int idx = blockIdx.x * blockDim.x + threadIdx.x;
    if (idx < DD * DD) {
        int d = idx >> 7, k = idx & 127;
        ((float*)g_Wt)[k * DD + d] = W[idx];
    }
}

// fp16 copy of x: idx over NN*32 float4s -> one uint2 (4 halfs) each
__global__ void k_xhalf(const float4* __restrict__ x4) {
    int idx = blockIdx.x * blockDim.x + threadIdx.x;
    if (idx < NN * 32) {
        float4 v = x4[idx];
        __half2 h0 = __floats2half2_rn(v.x, v.y);
        __half2 h1 = __floats2half2_rn(v.z, v.w);
        uint2 u;
        u.x = *(unsigned int*)&h0;
        u.y = *(unsigned int*)&h1;
        g_xh[idx] = u;
    }
}

// ---------------- gather: one warp per node, fp16 neighbor reads ----------------
#define GATHER_BLOCKS 1184
#define GATHER_WPB    8

__global__ void __launch_bounds__(256) k_gather(const float4* __restrict__ x4) {
    int lane = threadIdx.x & 31;
    int gw0  = blockIdx.x * GATHER_WPB + (threadIdx.x >> 5);
    const int nwarps = GATHER_BLOCKS * GATHER_WPB;

    for (int node = gw0; node < NN; node += nwarps) {
        float di = g_dinv[node];
        float4 acc = __ldg(&x4[node * 32 + lane]);       // self-loop term (fp32-exact)
        acc.x *= di; acc.y *= di; acc.z *= di; acc.w *= di;

        int beg = g_off[node], end = g_off[node + 1];
        for (int base = beg; base < end; base += 32) {
            int rem = end - base;
            int n = rem < 32 ? rem : 32;
            int   sidx = (lane < n) ? __ldg(&g_srcs[base + lane]) : 0;
            float sdi  = (lane < n) ? g_dinv[sidx] : 0.0f;
            #pragma unroll 8
            for (int jj = 0; jj < n; jj++) {
                int   s  = __shfl_sync(0xffffffffu, sidx, jj);
                float ws = __shfl_sync(0xffffffffu, sdi,  jj);
                uint2 hv = __ldg(&g_xh[s * 32 + lane]);
                float2 f0 = __half22float2(*(__half2*)&hv.x);
                float2 f1 = __half22float2(*(__half2*)&hv.y);
                acc.x += ws * f0.x; acc.y += ws * f0.y;
                acc.z += ws * f1.x; acc.w += ws * f1.y;
            }
        }
        acc.x *= di; acc.y *= di; acc.z *= di; acc.w *= di;
        g_agg[node * 32 + lane] = acc;
    }
}

// ---------------- GEMM(f32x2) + BN + ReLU + res + ReLU ----------------
#define GWARPS 8
#define RPW    8
#define CHUNK  (GWARPS * RPW)                 // 64
#define NCHUNK ((NN + CHUNK - 1) / CHUNK)     // 1563
#define GGRID  296

__global__ void __launch_bounds__(256, 2) k_gemm(
    const float4* __restrict__ x4,
    const float4* __restrict__ b4,  const float4* __restrict__ g4,
    const float4* __restrict__ be4, const float4* __restrict__ m4,
    const float4* __restrict__ v4,
    float4* __restrict__ out4)
{
    extern __shared__ float smem[];
    float4* sW4 = (float4*)smem;                       // Wt: 64KB
    float*  sXa = smem + DD * DD;                      // staging: 32KB
    __shared__ int s_chunk;

    int tid = threadIdx.x, lane = tid & 31, w = tid >> 5;
    int lrot = lane & 3;

    for (int i = tid; i < DD * DD / 4; i += 256) sW4[i] = g_Wt[i];

    float4 bb = __ldg(&b4[lane]);
    float4 gg = __ldg(&g4[lane]);
    float4 be = __ldg(&be4[lane]);
    float4 mm = __ldg(&m4[lane]);
    float4 vv = __ldg(&v4[lane]);
    float4 sc, sh;
    sc.x = gg.x * rsqrtf(vv.x + BN_EPS); sc.y = gg.y * rsqrtf(vv.y + BN_EPS);
    sc.z = gg.z * rsqrtf(vv.z + BN_EPS); sc.w = gg.w * rsqrtf(vv.w + BN_EPS);
    sh.x = (bb.x - mm.x) * sc.x + be.x;  sh.y = (bb.y - mm.y) * sc.y + be.y;
    sh.z = (bb.z - mm.z) * sc.z + be.z;  sh.w = (bb.w - mm.w) * sc.w + be.w;

    float* myX = sXa + w * (DD * RPW);
    __syncthreads();

    while (true) {
        if (tid == 0) s_chunk = atomicAdd(&g_tick, 1);
        __syncthreads();
        int chunk = s_chunk;
        if (chunk >= NCHUNK) break;
        int row0 = chunk * CHUNK + w * RPW;

        // ---- load 8 agg rows as 4 pairs; store pair-packed b64s (swizzled) ----
        #pragma unroll
        for (int j2 = 0; j2 < 4; j2++) {
            int nA = row0 + 2 * j2, nB = nA + 1;
            float4 a = (nA < NN) ? __ldg(&g_agg[nA * 32 + lane]) : make_float4(0.f,0.f,0.f,0.f);
            float4 b = (nB < NN) ? __ldg(&g_agg[nB * 32 + lane]) : make_float4(0.f,0.f,0.f,0.f);
            int rp = (j2 + lrot) & 3;
            float* base = myX + lane * 32 + 2 * rp;
            *(u64*)(base +  0) = packf2(a.x, b.x);
            *(u64*)(base +  8) = packf2(a.y, b.y);
            *(u64*)(base + 16) = packf2(a.z, b.z);
            *(u64*)(base + 24) = packf2(a.w, b.w);
        }
        __syncwarp();

        // ---- GEMM: 8 rows (4 f32x2 pairs) × 4 cols per thread ----
        u64 acc[4][4];
        #pragma unroll
        for (int j = 0; j < 4; j++)
            #pragma unroll
            for (int c = 0; c < 4; c++) acc[j][c] = 0ull;

        for (int kk = 0; kk < DD; kk += 16) {
            #pragma unroll
            for (int t = 0; t < 16; t++) {
                int k = kk + t;
                const float4 wv = sW4[k * 32 + lane];
                u64 w0 = packf2(wv.x, wv.x), w1 = packf2(wv.y, wv.y);
                u64 w2 = packf2(wv.z, wv.z), w3 = packf2(wv.w, wv.w);
                const ulonglong2 avA = *(const ulonglong2*)(myX + k * 8);
                const ulonglong2 avB = *(const ulonglong2*)(myX + k * 8 + 4);
                u64 sl[4] = {avA.x, avA.y, avB.x, avB.y};
                const int rot = (t >> 2) & 3;
                #pragma unroll
                for (int p = 0; p < 4; p++) {
                    const int j = (p + 4 - rot) & 3;
                    FMA2(acc[j][0], sl[p], w0);
                    FMA2(acc[j][1], sl[p], w1);
                    FMA2(acc[j][2], sl[p], w2);
                    FMA2(acc[j][3], sl[p], w3);
                }
            }
        }

        // ---- epilogue ----
        #pragma unroll
        for (int j = 0; j < 4; j++) {
            int rE = row0 + 2 * j, rO = rE + 1;
            float e0,o0,e1,o1,e2,o2,e3,o3;
            unpackf2(acc[j][0], e0, o0); unpackf2(acc[j][1], e1, o1);
            unpackf2(acc[j][2], e2, o2); unpackf2(acc[j][3], e3, o3);
            if (rE < NN) {
                float4 xv = __ldg(&x4[rE * 32 + lane]);
                float4 o;
                o.x = fmaxf(fmaxf(e0 * sc.x + sh.x, 0.f) + xv.x, 0.f);
                o.y = fmaxf(fmaxf(e1 * sc.y + sh.y, 0.f) + xv.y, 0.f);
                o.z = fmaxf(fmaxf(e2 * sc.z + sh.z, 0.f) + xv.z, 0.f);
                o.w = fmaxf(fmaxf(e3 * sc.w + sh.w, 0.f) + xv.w, 0.f);
                out4[rE * 32 + lane] = o;
            }
            if (rO < NN) {
                float4 xv = __ldg(&x4[rO * 32 + lane]);
                float4 o;
                o.x = fmaxf(fmaxf(o0 * sc.x + sh.x, 0.f) + xv.x, 0.f);
                o.y = fmaxf(fmaxf(o1 * sc.y + sh.y, 0.f) + xv.y, 0.f);
                o.z = fmaxf(fmaxf(o2 * sc.z + sh.z, 0.f) + xv.z, 0.f);
                o.w = fmaxf(fmaxf(o3 * sc.w + sh.w, 0.f) + xv.w, 0.f);
                out4[rO * 32 + lane] = o;
            }
        }
        __syncthreads();
    }
}

// ---------------- launch ----------------

extern "C" void kernel_launch(void* const* d_in, const int* in_sizes, int n_in,
                              void* d_out, int out_size) {
    const float* x     = (const float*)d_in[0];
    const int*   eidx  = (const int*)  d_in[1];   // [2][E]: row0 = src, row1 = dst
    const float* W     = (const float*)d_in[2];
    const float* b     = (const float*)d_in[3];
    const float* gamma = (const float*)d_in[4];
    const float* beta  = (const float*)d_in[5];
    const float* rmean = (const float*)d_in[6];
    const float* rvar  = (const float*)d_in[7];
    float* out = (float*)d_out;

    const int* src = eidx;
    const int* dst = eidx + NE;

    static void* degi_ptr = nullptr;
    static int smem_set = 0;
    int smem_bytes = (DD * DD + GWARPS * DD * RPW) * (int)sizeof(float);  // 98304
    if (!smem_set) {
        cudaGetSymbolAddress(&degi_ptr, g_degi);
        cudaFuncSetAttribute(k_gemm, cudaFuncAttributeMaxDynamicSharedMemorySize, smem_bytes);
        smem_set = 1;
    }

    cudaMemsetAsync(degi_ptr, 0, NN * sizeof(int));
    k_xhalf<<<(NN * 32 + 255) / 256, 256>>>((const float4*)x);   // overlaps count/scan chain
    k_count<<<(NE + 255) / 256, 256>>>(dst);
    k_scan1<<<NSCAN, 1024>>>();
    k_scan23<<<(NN + 255) / 256, 256>>>();
    k_bin<<<(NE + 255) / 256, 256>>>(src, dst);
    k_transpose<<<(DD * DD + 255) / 256, 256>>>(W);

    k_gather<<<GATHER_BLOCKS, 256>>>((const float4*)x);

    k_gemm<<<GGRID, 256, smem_bytes>>>((const float4*)x,
                                       (const float4*)b, (const float4*)gamma,
                                       (const float4*)beta, (const float4*)rmean,
                                       (const float4*)rvar, (float4*)out);
}

// round 7
// speedup vs baseline: 1.8683x; 1.0812x over previous
#include <cuda_runtime.h>
#include <cuda_fp16.h>

#define NN 100000
#define NE 1600000
#define DD 128
#define BN_EPS 1e-5f
#define NSCAN ((NN + 1023) / 1024)    // 98

typedef unsigned long long u64;

// ---- scratch (static device globals; no runtime allocation) ----
__device__ int    g_degi[NN];          // zero-initialized at load; re-zeroed by k_gemm
__device__ float  g_dinv[NN];
__device__ int    g_off[NN + 1];
__device__ int    g_offtmp[NN];
__device__ int    g_cursor[NN];
__device__ int    g_bsum[128];
__device__ int    g_tick;
__device__ int    g_srcs[NE];
__device__ uint2  g_xh[NN * 32];       // fp16 copy of x·dinv: [N][128] halfs
__device__ uint2  g_agg16[NN * 32];    // normalized aggregate, fp16 [N][128]
__device__ float4 g_Wt[DD * DD / 4];   // Wt[k][d] = W[d][k]

// ---------------- packed f32x2 helpers ----------------
__device__ __forceinline__ u64 packf2(float lo, float hi) {
    u64 r; asm("mov.b64 %0, {%1, %2};" : "=l"(r) : "f"(lo), "f"(hi)); return r;
}
__device__ __forceinline__ void unpackf2(u64 v, float& lo, float& hi) {
    asm("mov.b64 {%0, %1}, %2;" : "=f"(lo), "=f"(hi) : "l"(v));
}
#define FMA2(acc, a, b) asm("fma.rn.f32x2 %0, %1, %2, %0;" : "+l"(acc) : "l"(a), "l"(b))

// ---------------- prep ----------------

__global__ void k_count(const int* __restrict__ dst) {
    int e = blockIdx.x * blockDim.x + threadIdx.x;
    if (e < NE) atomicAdd(&g_degi[dst[e]], 1);
}

__global__ void k_scan1() {
    __shared__ int wsum[32];
    int tid = threadIdx.x;
    int gid = blockIdx.x * 1024 + tid;
    int v = (gid < NN) ? g_degi[gid] : 0;
    int x = v;
    #pragma unroll
    for (int o = 1; o < 32; o <<= 1) {
        int t = __shfl_up_sync(0xffffffffu, x, o);
        if ((tid & 31) >= o) x += t;
    }
    if ((tid & 31) == 31) wsum[tid >> 5] = x;
    __syncthreads();
    if (tid < 32) {
        int s = wsum[tid];
        #pragma unroll
        for (int o = 1; o < 32; o <<= 1) {
            int t = __shfl_up_sync(0xffffffffu, s, o);
            if (tid >= o) s += t;
        }
        wsum[tid] = s;
    }
    __syncthreads();
    int add  = (tid >= 32) ? wsum[(tid >> 5) - 1] : 0;
    int incl = x + add;
    if (gid < NN) g_offtmp[gid] = incl - v;
    if (tid == 1023) g_bsum[blockIdx.x] = incl;
}

// merged: every block scans the 98 block sums, then finalizes offsets/cursors/dinv
__global__ void k_scan23() {
    __shared__ int pre[NSCAN];
    __shared__ int wtot[4];
    int tid = threadIdx.x, lane = tid & 31, w = tid >> 5;

    if (tid < 128) {
        int v = (tid < NSCAN) ? g_bsum[tid] : 0;
        int x = v;
        #pragma unroll
        for (int o = 1; o < 32; o <<= 1) {
            int t = __shfl_up_sync(0xffffffffu, x, o);
            if (lane >= o) x += t;
        }
        if (lane == 31) wtot[w] = x;
        __syncwarp();
    }
    __syncthreads();
    if (tid == 0) {
        int run = 0;
        #pragma unroll
        for (int i = 0; i < 4; i++) { int q = wtot[i]; wtot[i] = run; run += q; }
    }
    __syncthreads();
    if (tid < 128) {
        int v = (tid < NSCAN) ? g_bsum[tid] : 0;
        int x = v;
        #pragma unroll
        for (int o = 1; o < 32; o <<= 1) {
            int t = __shfl_up_sync(0xffffffffu, x, o);
            if (lane >= o) x += t;
        }
        if (tid < NSCAN) pre[tid] = x - v + wtot[w];
    }
    __syncthreads();

    int i = blockIdx.x * blockDim.x + tid;
    if (i < NN) {
        int off = g_offtmp[i] + pre[i >> 10];
        g_off[i]    = off;
        g_cursor[i] = off;
        g_dinv[i]   = rsqrtf((float)g_degi[i] + 1.0f);
    }
    if (blockIdx.x == 0 && tid == 0) {
        g_off[NN] = NE;
        g_tick = 0;
    }
}

// merged: bin edges into CSR + build pre-scaled fp16 x copy + transpose W
// grid covers NN*32 = 3.2M threads
__global__ void k_prep2(const int* __restrict__ src, const int* __restrict__ dst,
                        const float4* __restrict__ x4, const float* __restrict__ W) {
    int idx = blockIdx.x * blockDim.x + threadIdx.x;

    if (idx < NE) {
        int d = dst[idx];
        int pos = atomicAdd(&g_cursor[d], 1);
        g_srcs[pos] = src[idx];
    }
    if (idx < NN * 32) {
        int node = idx >> 5;
        float di = g_dinv[node];
        float4 v = __ldg(&x4[idx]);
        __half2 h0 = __floats2half2_rn(v.x * di, v.y * di);
        __half2 h1 = __floats2half2_rn(v.z * di, v.w * di);
        uint2 u;
        u.x = *(unsigned int*)&h0;
        u.y = *(unsigned int*)&h1;
        g_xh[idx] = u;
    }
    if (idx < DD * DD) {
        int d = idx >> 7, k = idx & 127;
        ((float*)g_Wt)[k * DD + d] = W[idx];
    }
}

// ---------------- gather: one warp per node, pre-scaled fp16 rows ----------------
#define GATHER_BLOCKS 1184
#define GATHER_WPB    8

__global__ void __launch_bounds__(256) k_gather() {
    int lane = threadIdx.x & 31;
    int gw0  = blockIdx.x * GATHER_WPB + (threadIdx.x >> 5);
    const int nwarps = GATHER_BLOCKS * GATHER_WPB;

    for (int node = gw0; node < NN; node += nwarps) {
        float di = g_dinv[node];

        // self-loop term = xh[node] (already ×dinv[node])
        uint2 hs = __ldg(&g_xh[node * 32 + lane]);
        float2 s0 = __half22float2(*(__half2*)&hs.x);
        float2 s1 = __half22float2(*(__half2*)&hs.y);
        float4 acc = make_float4(s0.x, s0.y, s1.x, s1.y);

        int beg = g_off[node], end = g_off[node + 1];
        for (int base = beg; base < end; base += 32) {
            int rem = end - base;
            int n = rem < 32 ? rem : 32;
            int sidx = (lane < n) ? __ldg(&g_srcs[base + lane]) : 0;
            #pragma unroll 8
            for (int jj = 0; jj < n; jj++) {
                int s = __shfl_sync(0xffffffffu, sidx, jj);
                uint2 hv = __ldg(&g_xh[s * 32 + lane]);
                float2 f0 = __half22float2(*(__half2*)&hv.x);
                float2 f1 = __half22float2(*(__half2*)&hv.y);
                acc.x += f0.x; acc.y += f0.y;
                acc.z += f1.x; acc.w += f1.y;
            }
        }
        acc.x *= di; acc.y *= di; acc.z *= di; acc.w *= di;

        __half2 h0 = __floats2half2_rn(acc.x, acc.y);
        __half2 h1 = __floats2half2_rn(acc.z, acc.w);
        uint2 u;
        u.x = *(unsigned int*)&h0;
        u.y = *(unsigned int*)&h1;
        g_agg16[node * 32 + lane] = u;
    }
}

// ---------------- GEMM(f32x2) + BN + ReLU + res + ReLU ----------------
#define GWARPS 8
#define RPW    8
#define CHUNK  (GWARPS * RPW)                 // 64
#define NCHUNK ((NN + CHUNK - 1) / CHUNK)     // 1563
#define GGRID  296

__global__ void __launch_bounds__(256, 2) k_gemm(
    const float4* __restrict__ x4,
    const float4* __restrict__ b4,  const float4* __restrict__ g4,
    const float4* __restrict__ be4, const float4* __restrict__ m4,
    const float4* __restrict__ v4,
    float4* __restrict__ out4)
{
    extern __shared__ float smem[];
    float4* sW4 = (float4*)smem;                       // Wt: 64KB
    float*  sXa = smem + DD * DD;                      // staging: 32KB
    __shared__ int s_chunk;

    int tid = threadIdx.x, lane = tid & 31, w = tid >> 5;
    int lrot = lane & 3;

    // zero g_degi for next replay's k_count (stream-ordered; degi unused past scan23)
    for (int i = blockIdx.x * blockDim.x + tid; i < NN; i += gridDim.x * blockDim.x)
        g_degi[i] = 0;

    for (int i = tid; i < DD * DD / 4; i += 256) sW4[i] = g_Wt[i];

    float4 bb = __ldg(&b4[lane]);
    float4 gg = __ldg(&g4[lane]);
    float4 be = __ldg(&be4[lane]);
    float4 mm = __ldg(&m4[lane]);
    float4 vv = __ldg(&v4[lane]);
    float4 sc, sh;
    sc.x = gg.x * rsqrtf(vv.x + BN_EPS); sc.y = gg.y * rsqrtf(vv.y + BN_EPS);
    sc.z = gg.z * rsqrtf(vv.z + BN_EPS); sc.w = gg.w * rsqrtf(vv.w + BN_EPS);
    sh.x = (bb.x - mm.x) * sc.x + be.x;  sh.y = (bb.y - mm.y) * sc.y + be.y;
    sh.z = (bb.z - mm.z) * sc.z + be.z;  sh.w = (bb.w - mm.w) * sc.w + be.w;

    float* myX = sXa + w * (DD * RPW);
    __syncthreads();

    while (true) {
        if (tid == 0) s_chunk = atomicAdd(&g_tick, 1);
        __syncthreads();
        int chunk = s_chunk;
        if (chunk >= NCHUNK) break;
        int row0 = chunk * CHUNK + w * RPW;

        // ---- load 8 agg rows (fp16) as 4 pairs; store pair-packed b64s (swizzled) ----
        #pragma unroll
        for (int j2 = 0; j2 < 4; j2++) {
            int nA = row0 + 2 * j2, nB = nA + 1;
            uint2 hA = (nA < NN) ? __ldg(&g_agg16[nA * 32 + lane]) : make_uint2(0u, 0u);
            uint2 hB = (nB < NN) ? __ldg(&g_agg16[nB * 32 + lane]) : make_uint2(0u, 0u);
            float2 a01 = __half22float2(*(__half2*)&hA.x);
            float2 a23 = __half22float2(*(__half2*)&hA.y);
            float2 b01 = __half22float2(*(__half2*)&hB.x);
            float2 b23 = __half22float2(*(__half2*)&hB.y);
            int rp = (j2 + lrot) & 3;
            float* base = myX + lane * 32 + 2 * rp;
            *(u64*)(base +  0) = packf2(a01.x, b01.x);
            *(u64*)(base +  8) = packf2(a01.y, b01.y);
            *(u64*)(base + 16) = packf2(a23.x, b23.x);
            *(u64*)(base + 24) = packf2(a23.y, b23.y);
        }
        __syncwarp();

        // ---- GEMM: 8 rows (4 f32x2 pairs) × 4 cols per thread ----
        u64 acc[4][4];
        #pragma unroll
        for (int j = 0; j < 4; j++)
            #pragma unroll
            for (int c = 0; c < 4; c++) acc[j][c] = 0ull;

        for (int kk = 0; kk < DD; kk += 16) {
            #pragma unroll
            for (int t = 0; t < 16; t++) {
                int k = kk + t;
                const float4 wv = sW4[k * 32 + lane];
                u64 w0 = packf2(wv.x, wv.x), w1 = packf2(wv.y, wv.y);
                u64 w2 = packf2(wv.z, wv.z), w3 = packf2(wv.w, wv.w);
                const ulonglong2 avA = *(const ulonglong2*)(myX + k * 8);
                const ulonglong2 avB = *(const ulonglong2*)(myX + k * 8 + 4);
                u64 sl[4] = {avA.x, avA.y, avB.x, avB.y};
                const int rot = (t >> 2) & 3;
                #pragma unroll
                for (int p = 0; p < 4; p++) {
                    const int j = (p + 4 - rot) & 3;
                    FMA2(acc[j][0], sl[p], w0);
                    FMA2(acc[j][1], sl[p], w1);
                    FMA2(acc[j][2], sl[p], w2);
                    FMA2(acc[j][3], sl[p], w3);
                }
            }
        }

        // ---- epilogue ----
        #pragma unroll
        for (int j = 0; j < 4; j++) {
            int rE = row0 + 2 * j, rO = rE + 1;
            float e0,o0,e1,o1,e2,o2,e3,o3;
            unpackf2(acc[j][0], e0, o0); unpackf2(acc[j][1], e1, o1);
            unpackf2(acc[j][2], e2, o2); unpackf2(acc[j][3], e3, o3);
            if (rE < NN) {
                float4 xv = __ldg(&x4[rE * 32 + lane]);
                float4 o;
                o.x = fmaxf(fmaxf(e0 * sc.x + sh.x, 0.f) + xv.x, 0.f);
                o.y = fmaxf(fmaxf(e1 * sc.y + sh.y, 0.f) + xv.y, 0.f);
                o.z = fmaxf(fmaxf(e2 * sc.z + sh.z, 0.f) + xv.z, 0.f);
                o.w = fmaxf(fmaxf(e3 * sc.w + sh.w, 0.f) + xv.w, 0.f);
                out4[rE * 32 + lane] = o;
            }
            if (rO < NN) {
                float4 xv = __ldg(&x4[rO * 32 + lane]);
                float4 o;
                o.x = fmaxf(fmaxf(o0 * sc.x + sh.x, 0.f) + xv.x, 0.f);
                o.y = fmaxf(fmaxf(o1 * sc.y + sh.y, 0.f) + xv.y, 0.f);
                o.z = fmaxf(fmaxf(o2 * sc.z + sh.z, 0.f) + xv.z, 0.f);
                o.w = fmaxf(fmaxf(o3 * sc.w + sh.w, 0.f) + xv.w, 0.f);
                out4[rO * 32 + lane] = o;
            }
        }
        __syncthreads();
    }
}

// ---------------- launch ----------------

extern "C" void kernel_launch(void* const* d_in, const int* in_sizes, int n_in,
                              void* d_out, int out_size) {
    const float* x     = (const float*)d_in[0];
    const int*   eidx  = (const int*)  d_in[1];   // [2][E]: row0 = src, row1 = dst
    const float* W     = (const float*)d_in[2];
    const float* b     = (const float*)d_in[3];
    const float* gamma = (const float*)d_in[4];
    const float* beta  = (const float*)d_in[5];
    const float* rmean = (const float*)d_in[6];
    const float* rvar  = (const float*)d_in[7];
    float* out = (float*)d_out;

    const int* src = eidx;
    const int* dst = eidx + NE;

    static int smem_set = 0;
    int smem_bytes = (DD * DD + GWARPS * DD * RPW) * (int)sizeof(float);  // 98304
    if (!smem_set) {
        cudaFuncSetAttribute(k_gemm, cudaFuncAttributeMaxDynamicSharedMemorySize, smem_bytes);
        smem_set = 1;
    }

    // g_degi is zeroed at module load and re-zeroed at the end of each replay by k_gemm
    k_count<<<(NE + 255) / 256, 256>>>(dst);                     // launch 1
    k_scan1<<<NSCAN, 1024>>>();                                  // launch 2
    k_scan23<<<(NN + 255) / 256, 256>>>();                       // launch 3
    k_prep2<<<(NN * 32 + 255) / 256, 256>>>(src, dst,            // launch 4
                                            (const float4*)x, W);
    k_gather<<<GATHER_BLOCKS, 256>>>();                          // launch 5 (ncu target)
    k_gemm<<<GGRID, 256, smem_bytes>>>((const float4*)x,         // launch 6
                                       (const float4*)b, (const float4*)gamma,
                                       (const float4*)beta, (const float4*)rmean,
                                       (const float4*)rvar, (float4*)out);
}

// round 8
// speedup vs baseline: 2.4342x; 1.3029x over previous
#include <cuda_runtime.h>
#include <cuda_fp16.h>

#define NN 100000
#define NE 1600000
#define DD 128
#define BN_EPS 1e-5f
#define NSCAN ((NN + 1023) / 1024)    // 98

typedef unsigned long long u64;

// ---- scratch (static device globals; no runtime allocation) ----
__device__ int    g_degi[NN];          // zeroed at load; re-zeroed by k_gemm prologue
__device__ float  g_dinv[NN];
__device__ int    g_off[NN + 1];
__device__ int    g_offtmp[NN];
__device__ int    g_cursor[NN];
__device__ int    g_bsum[128];
__device__ int    g_tick;
__device__ int    g_srcs[NE];
__device__ uint2  g_xh[NN * 32];       // fp16 x·dinv: [N][128] halfs
__device__ uint4  g_agg16[NN * 16];    // fp16 normalized aggregate [N][128] (16B-aligned)
__device__ uint2  g_bfrag[8 * 16 * 32];// precomputed mma B fragments: [kstep][ntile][lane]
__device__ float2 g_sc2[64];           // BN scale per col pair
__device__ float2 g_sh2[64];           // BN shift per col pair

// ---------------- prep ----------------

__global__ void k_count(const int* __restrict__ dst) {
    int e = blockIdx.x * blockDim.x + threadIdx.x;
    if (e < NE) atomicAdd(&g_degi[dst[e]], 1);
}

__global__ void k_scan1() {
    __shared__ int wsum[32];
    int tid = threadIdx.x;
    int gid = blockIdx.x * 1024 + tid;
    int v = (gid < NN) ? g_degi[gid] : 0;
    int x = v;
    #pragma unroll
    for (int o = 1; o < 32; o <<= 1) {
        int t = __shfl_up_sync(0xffffffffu, x, o);
        if ((tid & 31) >= o) x += t;
    }
    if ((tid & 31) == 31) wsum[tid >> 5] = x;
    __syncthreads();
    if (tid < 32) {
        int s = wsum[tid];
        #pragma unroll
        for (int o = 1; o < 32; o <<= 1) {
            int t = __shfl_up_sync(0xffffffffu, s, o);
            if (tid >= o) s += t;
        }
        wsum[tid] = s;
    }
    __syncthreads();
    int add  = (tid >= 32) ? wsum[(tid >> 5) - 1] : 0;
    int incl = x + add;
    if (gid < NN) g_offtmp[gid] = incl - v;
    if (tid == 1023) g_bsum[blockIdx.x] = incl;
}

__global__ void k_scan23() {
    __shared__ int pre[NSCAN];
    __shared__ int wtot[4];
    int tid = threadIdx.x, lane = tid & 31, w = tid >> 5;

    if (tid < 128) {
        int v = (tid < NSCAN) ? g_bsum[tid] : 0;
        int x = v;
        #pragma unroll
        for (int o = 1; o < 32; o <<= 1) {
            int t = __shfl_up_sync(0xffffffffu, x, o);
            if (lane >= o) x += t;
        }
        if (lane == 31) wtot[w] = x;
        __syncwarp();
    }
    __syncthreads();
    if (tid == 0) {
        int run = 0;
        #pragma unroll
        for (int i = 0; i < 4; i++) { int q = wtot[i]; wtot[i] = run; run += q; }
    }
    __syncthreads();
    if (tid < 128) {
        int v = (tid < NSCAN) ? g_bsum[tid] : 0;
        int x = v;
        #pragma unroll
        for (int o = 1; o < 32; o <<= 1) {
            int t = __shfl_up_sync(0xffffffffu, x, o);
            if (lane >= o) x += t;
        }
        if (tid < NSCAN) pre[tid] = x - v + wtot[w];
    }
    __syncthreads();

    int i = blockIdx.x * blockDim.x + tid;
    if (i < NN) {
        int off = g_offtmp[i] + pre[i >> 10];
        g_off[i]    = off;
        g_cursor[i] = off;
        g_dinv[i]   = rsqrtf((float)g_degi[i] + 1.0f);
    }
    if (blockIdx.x == 0 && tid == 0) {
        g_off[NN] = NE;
        g_tick = 0;
    }
}

// merged: CSR bin + fp16 x·dinv copy + mma B-fragment build + BN const tables
__global__ void k_prep2(const int* __restrict__ src, const int* __restrict__ dst,
                        const float4* __restrict__ x4, const float* __restrict__ W,
                        const float* __restrict__ bia, const float* __restrict__ gam,
                        const float* __restrict__ bet, const float* __restrict__ rme,
                        const float* __restrict__ rva) {
    int idx = blockIdx.x * blockDim.x + threadIdx.x;

    if (idx < NE) {
        int d = dst[idx];
        int pos = atomicAdd(&g_cursor[d], 1);
        g_srcs[pos] = src[idx];
    }
    if (idx < NN * 32) {
        int node = idx >> 5;
        float di = g_dinv[node];
        float4 v = __ldg(&x4[idx]);
        __half2 h0 = __floats2half2_rn(v.x * di, v.y * di);
        __half2 h1 = __floats2half2_rn(v.z * di, v.w * di);
        uint2 u;
        u.x = *(unsigned int*)&h0;
        u.y = *(unsigned int*)&h1;
        g_xh[idx] = u;
    }
    if (idx < 8 * 16 * 32) {
        // B fragment for mma.m16n8k16 (col-major B): lane holds
        // b0 = {B[k0][n], B[k0+1][n]}, b1 = {B[k0+8][n], B[k0+9][n]}
        // B[k][n] = W[n][k]  (W is [out=n][in=k], row-major)
        int lane = idx & 31, nt = (idx >> 5) & 15, ks = idx >> 9;
        int n  = nt * 8 + (lane >> 2);
        int k0 = ks * 16 + (lane & 3) * 2;
        const float* wr = W + n * DD;
        __half2 b0 = __floats2half2_rn(wr[k0],     wr[k0 + 1]);
        __half2 b1 = __floats2half2_rn(wr[k0 + 8], wr[k0 + 9]);
        uint2 u;
        u.x = *(unsigned int*)&b0;
        u.y = *(unsigned int*)&b1;
        g_bfrag[idx] = u;
    }
    if (idx < 64) {
        float2 gg = ((const float2*)gam)[idx];
        float2 vv = ((const float2*)rva)[idx];
        float2 bb = ((const float2*)bia)[idx];
        float2 mm = ((const float2*)rme)[idx];
        float2 be = ((const float2*)bet)[idx];
        float2 sc, sh;
        sc.x = gg.x * rsqrtf(vv.x + BN_EPS);
        sc.y = gg.y * rsqrtf(vv.y + BN_EPS);
        sh.x = (bb.x - mm.x) * sc.x + be.x;
        sh.y = (bb.y - mm.y) * sc.y + be.y;
        g_sc2[idx] = sc;
        g_sh2[idx] = sh;
    }
}

// ---------------- gather: one warp per node, pre-scaled fp16 rows ----------------
#define GATHER_BLOCKS 1184
#define GATHER_WPB    8

__global__ void __launch_bounds__(256) k_gather() {
    int lane = threadIdx.x & 31;
    int gw0  = blockIdx.x * GATHER_WPB + (threadIdx.x >> 5);
    const int nwarps = GATHER_BLOCKS * GATHER_WPB;

    for (int node = gw0; node < NN; node += nwarps) {
        float di = g_dinv[node];

        uint2 hs = __ldg(&g_xh[node * 32 + lane]);
        float2 s0 = __half22float2(*(__half2*)&hs.x);
        float2 s1 = __half22float2(*(__half2*)&hs.y);
        float4 acc = make_float4(s0.x, s0.y, s1.x, s1.y);

        int beg = g_off[node], end = g_off[node + 1];
        for (int base = beg; base < end; base += 32) {
            int rem = end - base;
            int n = rem < 32 ? rem : 32;
            int sidx = (lane < n) ? __ldg(&g_srcs[base + lane]) : 0;
            #pragma unroll 8
            for (int jj = 0; jj < n; jj++) {
                int s = __shfl_sync(0xffffffffu, sidx, jj);
                uint2 hv = __ldg(&g_xh[s * 32 + lane]);
                float2 f0 = __half22float2(*(__half2*)&hv.x);
                float2 f1 = __half22float2(*(__half2*)&hv.y);
                acc.x += f0.x; acc.y += f0.y;
                acc.z += f1.x; acc.w += f1.y;
            }
        }
        acc.x *= di; acc.y *= di; acc.z *= di; acc.w *= di;

        __half2 h0 = __floats2half2_rn(acc.x, acc.y);
        __half2 h1 = __floats2half2_rn(acc.z, acc.w);
        uint2 u;
        u.x = *(unsigned int*)&h0;
        u.y = *(unsigned int*)&h1;
        ((uint2*)g_agg16)[node * 32 + lane] = u;
    }
}

// ---------------- tensor-core GEMM (mma.sync fp16) + BN + ReLU + res + ReLU ----
#define CROWS 128
#define NCH   ((NN + CROWS - 1) / CROWS)   // 782
#define GGRID 296

__global__ void __launch_bounds__(256, 2) k_gemm(
    const float2* __restrict__ x2, float2* __restrict__ out2)
{
    __shared__ __align__(16) char sAraw[CROWS * 256];   // 32KB fp16 A chunk, swizzled
    __shared__ int s_chunk;

    int tid = threadIdx.x, lane = tid & 31, w = tid >> 5;

    // zero g_degi for next replay's k_count (stream-ordered)
    for (int i = blockIdx.x * blockDim.x + tid; i < NN; i += gridDim.x * blockDim.x)
        g_degi[i] = 0;

    unsigned int sA;
    { unsigned long long t;
      asm("cvta.to.shared.u64 %0, %1;" : "=l"(t) : "l"(sAraw));
      sA = (unsigned int)t; }

    // ldmatrix per-lane row mapping: tile = lane/8; rows interleave, granule selects k-half
    int rloc  = w * 16 + ((lane >> 3) & 1) * 8 + (lane & 7);  // smem row for this lane
    int gsel  = lane >> 4;                                    // granule offset (tile>>1)

    const uint4* aggv = g_agg16;

    while (true) {
        if (tid == 0) s_chunk = atomicAdd(&g_tick, 1);
        __syncthreads();
        int chunk = s_chunk;
        if (chunk >= NCH) break;
        int row0 = chunk * CROWS;

        // ---- stage A chunk (guarded), XOR-swizzled 16B granules ----
        #pragma unroll
        for (int ii = 0; ii < 8; ii++) {
            int i = tid + ii * 256;                 // 2048 granules
            int r = i >> 4, c = i & 15;
            int grow = row0 + r;
            uint4 v = (grow < NN) ? __ldg(&aggv[grow * 16 + c])
                                  : make_uint4(0u, 0u, 0u, 0u);
            int sw = (c & 8) | ((c ^ r) & 7);
            *(uint4*)(sAraw + r * 256 + sw * 16) = v;
        }
        __syncthreads();

        float acc[16][4];
        #pragma unroll
        for (int nt = 0; nt < 16; nt++)
            #pragma unroll
            for (int q = 0; q < 4; q++) acc[nt][q] = 0.0f;

        #pragma unroll
        for (int ks = 0; ks < 8; ks++) {
            int c = ks * 2 + gsel;
            int sw = (c & 8) | ((c ^ rloc) & 7);
            unsigned int addr = sA + rloc * 256 + sw * 16;
            unsigned int a0, a1, a2, a3;
            asm volatile("ldmatrix.sync.aligned.m8n8.x4.shared.b16 {%0,%1,%2,%3}, [%4];"
                         : "=r"(a0), "=r"(a1), "=r"(a2), "=r"(a3) : "r"(addr));
            #pragma unroll
            for (int nt = 0; nt < 16; nt++) {
                uint2 b = __ldg(&g_bfrag[(ks * 16 + nt) * 32 + lane]);
                asm volatile(
                    "mma.sync.aligned.m16n8k16.row.col.f32.f16.f16.f32 "
                    "{%0,%1,%2,%3}, {%4,%5,%6,%7}, {%8,%9}, {%0,%1,%2,%3};"
                    : "+f"(acc[nt][0]), "+f"(acc[nt][1]), "+f"(acc[nt][2]), "+f"(acc[nt][3])
                    : "r"(a0), "r"(a1), "r"(a2), "r"(a3), "r"(b.x), "r"(b.y));
            }
        }

        // ---- epilogue: d layout (r,c),(r,c+1),(r+8,c),(r+8,c+1); r=lane/4, c=(lane%4)*2
        int rA = row0 + w * 16 + (lane >> 2);
        int rB = rA + 8;
        int ci = lane & 3;
        #pragma unroll
        for (int nt = 0; nt < 16; nt++) {
            int cp = nt * 4 + ci;                  // float2 column index
            float2 sc = __ldg(&g_sc2[cp]);
            float2 sh = __ldg(&g_sh2[cp]);
            if (rA < NN) {
                float2 xv = __ldg(&x2[rA * 64 + cp]);
                float2 o;
                o.x = fmaxf(fmaxf(acc[nt][0] * sc.x + sh.x, 0.f) + xv.x, 0.f);
                o.y = fmaxf(fmaxf(acc[nt][1] * sc.y + sh.y, 0.f) + xv.y, 0.f);
                out2[rA * 64 + cp] = o;
            }
            if (rB < NN) {
                float2 xv = __ldg(&x2[rB * 64 + cp]);
                float2 o;
                o.x = fmaxf(fmaxf(acc[nt][2] * sc.x + sh.x, 0.f) + xv.x, 0.f);
                o.y = fmaxf(fmaxf(acc[nt][3] * sc.y + sh.y, 0.f) + xv.y, 0.f);
                out2[rB * 64 + cp] = o;
            }
        }
        __syncthreads();
    }
}

// ---------------- launch ----------------

extern "C" void kernel_launch(void* const* d_in, const int* in_sizes, int n_in,
                              void* d_out, int out_size) {
    const float* x     = (const float*)d_in[0];
    const int*   eidx  = (const int*)  d_in[1];   // [2][E]: row0 = src, row1 = dst
    const float* W     = (const float*)d_in[2];
    const float* b     = (const float*)d_in[3];
    const float* gamma = (const float*)d_in[4];
    const float* beta  = (const float*)d_in[5];
    const float* rmean = (const float*)d_in[6];
    const float* rvar  = (const float*)d_in[7];
    float* out = (float*)d_out;

    const int* src = eidx;
    const int* dst = eidx + NE;

    k_count<<<(NE + 255) / 256, 256>>>(dst);
    k_scan1<<<NSCAN, 1024>>>();
    k_scan23<<<(NN + 255) / 256, 256>>>();
    k_prep2<<<(NN * 32 + 255) / 256, 256>>>(src, dst, (const float4*)x, W,
                                            b, gamma, beta, rmean, rvar);
    k_gather<<<GATHER_BLOCKS, 256>>>();
    k_gemm<<<GGRID, 256>>>((const float2*)x, (float2*)out);
}